// round 7
// baseline (speedup 1.0000x reference)
#include <cuda_runtime.h>
#include <cstdint>
#include <cstddef>

#define B_   2048
#define E_   512
#define EMB_ 256
#define AR_  1024
#define H256_ 256
#define H32_  32
#define NT_   256

// Scratch (no cudaMalloc allowed)
__device__ float g_W12[AR_ * H32_];  // W_fc1 @ W_fc2
__device__ float g_bvec[H32_];       // b_fc1 @ W_fc2 + b_fc2
__device__ float g_u[B_ * H32_];     // ar[b] @ W12 + bvec

// ---------------------------------------------------------------------------
// Threefry2x32-20, JAX partitionable variant: counter (hi=0, lo=index),
// output = out0 ^ out1, key = (0, 42).
// ---------------------------------------------------------------------------
__device__ __forceinline__ uint32_t rotl32(uint32_t x, int r) {
    return (x << r) | (x >> (32 - r));
}

__device__ __forceinline__ uint32_t threefry_bits(uint32_t k0, uint32_t k1,
                                                  uint32_t c0, uint32_t c1) {
    uint32_t ks2 = k0 ^ k1 ^ 0x1BD11BDAu;
    uint32_t x0 = c0 + k0;
    uint32_t x1 = c1 + k1;
#define TF_RND(r) { x0 += x1; x1 = rotl32(x1, (r)); x1 ^= x0; }
    TF_RND(13) TF_RND(15) TF_RND(26) TF_RND(6)
    x0 += k1;  x1 += ks2 + 1u;
    TF_RND(17) TF_RND(29) TF_RND(16) TF_RND(24)
    x0 += ks2; x1 += k0 + 2u;
    TF_RND(13) TF_RND(15) TF_RND(26) TF_RND(6)
    x0 += k0;  x1 += k1 + 3u;
    TF_RND(17) TF_RND(29) TF_RND(16) TF_RND(24)
    x0 += k1;  x1 += ks2 + 4u;
    TF_RND(13) TF_RND(15) TF_RND(26) TF_RND(6)
    x0 += ks2; x1 += k0 + 5u;
#undef TF_RND
    return x0 ^ x1;
}

__device__ __forceinline__ float gumbel_from_index(uint32_t idx) {
    uint32_t bits = threefry_bits(0u, 42u, 0u, idx);
    float u = __uint_as_float((bits >> 9) | 0x3f800000u) - 1.0f;
    const float tiny = 1.17549435e-38f;
    u = fmaxf(tiny, u + tiny);
    return -logf(-logf(u));
}

// ---------------------------------------------------------------------------
// P0: g_W12 = W_fc1 @ W_fc2 (1024x32), g_bvec. Warp-per-row, unroll 16.
// ---------------------------------------------------------------------------
__global__ __launch_bounds__(256)
void kernelP0(const float* __restrict__ W_fc1, const float* __restrict__ W_fc2,
              const float* __restrict__ b_fc1, const float* __restrict__ b_fc2) {
    const int warp = threadIdx.x >> 5;
    const int lane = threadIdx.x & 31;
    const int r = blockIdx.x * 8 + warp;

    const float* frow = W_fc1 + r * H256_;
    float a0 = 0.f, a1 = 0.f, a2 = 0.f, a3 = 0.f;
#pragma unroll
    for (int k = 0; k < H256_; k += 16) {
        float4 f0 = *(const float4*)(frow + k);
        float4 f1 = *(const float4*)(frow + k + 4);
        float4 f2 = *(const float4*)(frow + k + 8);
        float4 f3 = *(const float4*)(frow + k + 12);
        a0 += f0.x * W_fc2[(k + 0) * H32_ + lane]
            + f1.x * W_fc2[(k + 4) * H32_ + lane]
            + f2.x * W_fc2[(k + 8) * H32_ + lane]
            + f3.x * W_fc2[(k + 12) * H32_ + lane];
        a1 += f0.y * W_fc2[(k + 1) * H32_ + lane]
            + f1.y * W_fc2[(k + 5) * H32_ + lane]
            + f2.y * W_fc2[(k + 9) * H32_ + lane]
            + f3.y * W_fc2[(k + 13) * H32_ + lane];
        a2 += f0.z * W_fc2[(k + 2) * H32_ + lane]
            + f1.z * W_fc2[(k + 6) * H32_ + lane]
            + f2.z * W_fc2[(k + 10) * H32_ + lane]
            + f3.z * W_fc2[(k + 14) * H32_ + lane];
        a3 += f0.w * W_fc2[(k + 3) * H32_ + lane]
            + f1.w * W_fc2[(k + 7) * H32_ + lane]
            + f2.w * W_fc2[(k + 11) * H32_ + lane]
            + f3.w * W_fc2[(k + 15) * H32_ + lane];
    }
    g_W12[r * H32_ + lane] = (a0 + a1) + (a2 + a3);

    if (blockIdx.x == 0 && warp == 0) {
        float b0 = b_fc2[lane];
#pragma unroll 8
        for (int k = 0; k < H256_; k++) b0 += b_fc1[k] * W_fc2[k * H32_ + lane];
        g_bvec[lane] = b0;
    }
}

// ---------------------------------------------------------------------------
// P1: g_u[b] = ar[b] @ W12 + bvec. 4 b's per block, 2 warps per b.
// ---------------------------------------------------------------------------
__global__ __launch_bounds__(256)
void kernelP1(const float* __restrict__ ar) {
    const int warp = threadIdx.x >> 5;
    const int lane = threadIdx.x & 31;
    const int q = warp & 3;
    const int half = warp >> 2;
    const int b0 = blockIdx.x * 4;

    __shared__ float s_p[2][4][32];

    const float* arow = ar + (size_t)(b0 + q) * AR_ + half * 512;
    const float* wp = g_W12 + (half * 512) * H32_;
    float a0 = 0.f, a1 = 0.f, a2 = 0.f, a3 = 0.f;
#pragma unroll 8
    for (int r = 0; r < 512; r += 4) {
        float4 a = *(const float4*)(arow + r);
        a0 += a.x * wp[(r + 0) * H32_ + lane];
        a1 += a.y * wp[(r + 1) * H32_ + lane];
        a2 += a.z * wp[(r + 2) * H32_ + lane];
        a3 += a.w * wp[(r + 3) * H32_ + lane];
    }
    s_p[half][q][lane] = (a0 + a1) + (a2 + a3);
    __syncthreads();

    if (warp < 4)
        g_u[(b0 + warp) * H32_ + lane] =
            s_p[0][warp][lane] + s_p[1][warp][lane] + g_bvec[lane];
}

// ---------------------------------------------------------------------------
// BF4: fused, 4 b's per block, grid 512.
// Prologue: dense W_func pass (4 mask accumulators) -> t; z2 partials
// (8-warp x 4 b); LSTM (4 warps); w = W_conv@q. Then stream 4 b's.
// ---------------------------------------------------------------------------
__global__ __launch_bounds__(256)
void kernelBF4(const int* __restrict__ utm, const int* __restrict__ tum,
               const float* __restrict__ ee,
               const float* __restrict__ W_func, const float* __restrict__ b_func,
               const float* __restrict__ W_conv, const float* __restrict__ b_conv,
               const float* __restrict__ W_fc2,
               const float* __restrict__ lk, const float* __restrict__ lb,
               float* __restrict__ out, int mode) {
    const int b0 = blockIdx.x * 4;
    const int tid = threadIdx.x;
    const int warp = tid >> 5;
    const int lane = tid & 31;

    __shared__ float s_m[4][NT_];
    __shared__ float s_t[4][H256_];
    __shared__ float s_p[4][8][32];
    __shared__ float s_q[4][32];
    __shared__ float s_w[4][EMB_];
    __shared__ float s_c0[4];
    __shared__ float ys[512];
    __shared__ float wred[8];
    __shared__ float wred2[8];
    __shared__ float wv[8];
    __shared__ int   wi[8];

    // ---- masks ----
#pragma unroll
    for (int q = 0; q < 4; q++)
        s_m[q][tid] = (float)utm[(b0 + q) * NT_ + tid];
    __syncthreads();

    // ---- t: dense W_func pass, 8 loads in flight, 4 b accumulators ----
    {
        float ta[4][2];
#pragma unroll
        for (int q = 0; q < 4; q++) { ta[q][0] = 0.f; ta[q][1] = 0.f; }
#pragma unroll
        for (int kk = 0; kk < NT_; kk += 8) {
            float wv8[8];
#pragma unroll
            for (int i = 0; i < 8; i++)
                wv8[i] = W_func[(kk + i) * H256_ + tid];   // coalesced
#pragma unroll
            for (int i = 0; i < 8; i += 2) {
#pragma unroll
                for (int q = 0; q < 4; q++) {
                    ta[q][0] += wv8[i + 0] * s_m[q][kk + i + 0];
                    ta[q][1] += wv8[i + 1] * s_m[q][kk + i + 1];
                }
            }
        }
        const float bf = b_func[tid];
#pragma unroll
        for (int q = 0; q < 4; q++)
            s_t[q][tid] = fmaxf(ta[q][0] + ta[q][1] + bf, 0.0f);
    }
    __syncthreads();

    // ---- z2 partials: warp w covers W_fc2 rows w*32..+31, 4 b's ----
    {
        float p0 = 0.f, p1 = 0.f, p2 = 0.f, p3 = 0.f;
#pragma unroll
        for (int jj = 0; jj < 32; jj++) {
            const int j = warp * 32 + jj;
            const float wf = W_fc2[j * H32_ + lane];
            p0 += s_t[0][j] * wf;
            p1 += s_t[1][j] * wf;
            p2 += s_t[2][j] * wf;
            p3 += s_t[3][j] * wf;
        }
        s_p[0][warp][lane] = p0;
        s_p[1][warp][lane] = p1;
        s_p[2][warp][lane] = p2;
        s_p[3][warp][lane] = p3;
    }
    __syncthreads();

    // ---- LSTM: warps 0..3, b = b0 + warp ----
    if (warp < 4) {
        float z = g_u[(b0 + warp) * H32_ + lane];   // includes bvec
#pragma unroll
        for (int w2 = 0; w2 < 8; w2++) z += s_p[warp][w2][lane];
        float zi = lb[lane];
        float zg = lb[64 + lane];
        float zo = lb[96 + lane];
#pragma unroll
        for (int m = 0; m < 32; m++) {
            float v = __shfl_sync(0xffffffffu, z, m);
            zi += v * lk[m * 128 + lane];
            zg += v * lk[m * 128 + 64 + lane];
            zo += v * lk[m * 128 + 96 + lane];
        }
        float ig = 1.0f / (1.0f + expf(-zi));
        float gg = tanhf(zg);
        float og = 1.0f / (1.0f + expf(-zo));
        float c  = ig * gg;
        float h  = og * tanhf(c);
        s_q[warp][lane] = h;
        float part = b_conv[lane] * h;
#pragma unroll
        for (int s = 16; s > 0; s >>= 1) part += __shfl_xor_sync(0xffffffffu, part, s);
        if (lane == 0) s_c0[warp] = part;
    }
    __syncthreads();

    // ---- w = W_conv @ q, row per thread, shared across 4 b's ----
    {
        const float* wr = W_conv + tid * H32_;
        float4 wc[8];
#pragma unroll
        for (int m = 0; m < 8; m++) wc[m] = *(const float4*)(wr + m * 4);
#pragma unroll
        for (int q = 0; q < 4; q++) {
            float s0 = 0.f, s1 = 0.f;
#pragma unroll
            for (int m = 0; m < 8; m++) {
                s0 += wc[m].x * s_q[q][m * 4 + 0] + wc[m].y * s_q[q][m * 4 + 1];
                s1 += wc[m].z * s_q[q][m * 4 + 2] + wc[m].w * s_q[q][m * 4 + 3];
            }
            s_w[q][tid] = s0 + s1;
        }
    }
    __syncthreads();

    // =========================== Stream 4 b's ===========================
    for (int q = 0; q < 4; q++) {
        const int b = b0 + q;
        const float4 w0 = *(const float4*)(&s_w[q][4 * lane]);
        const float4 w1 = *(const float4*)(&s_w[q][128 + 4 * lane]);
        const float cb = s_c0[q];
        const int tm = tum[b];
        const float4* eb = (const float4*)(ee + (size_t)b * E_ * EMB_);

#pragma unroll
        for (int it = 0; it < 16; it++) {
            const int e0 = it * 32 + warp * 4;
            float4 r0a = __ldcs(eb + (size_t)(e0 + 0) * 64 + lane);
            float4 r0b = __ldcs(eb + (size_t)(e0 + 0) * 64 + 32 + lane);
            float4 r1a = __ldcs(eb + (size_t)(e0 + 1) * 64 + lane);
            float4 r1b = __ldcs(eb + (size_t)(e0 + 1) * 64 + 32 + lane);
            float4 r2a = __ldcs(eb + (size_t)(e0 + 2) * 64 + lane);
            float4 r2b = __ldcs(eb + (size_t)(e0 + 2) * 64 + 32 + lane);
            float4 r3a = __ldcs(eb + (size_t)(e0 + 3) * 64 + lane);
            float4 r3b = __ldcs(eb + (size_t)(e0 + 3) * 64 + 32 + lane);

            float s0 = r0a.x * w0.x + r0a.y * w0.y + r0a.z * w0.z + r0a.w * w0.w
                     + r0b.x * w1.x + r0b.y * w1.y + r0b.z * w1.z + r0b.w * w1.w;
            float s1 = r1a.x * w0.x + r1a.y * w0.y + r1a.z * w0.z + r1a.w * w0.w
                     + r1b.x * w1.x + r1b.y * w1.y + r1b.z * w1.z + r1b.w * w1.w;
            float s2 = r2a.x * w0.x + r2a.y * w0.y + r2a.z * w0.z + r2a.w * w0.w
                     + r2b.x * w1.x + r2b.y * w1.y + r2b.z * w1.z + r2b.w * w1.w;
            float s3 = r3a.x * w0.x + r3a.y * w0.y + r3a.z * w0.z + r3a.w * w0.w
                     + r3b.x * w1.x + r3b.y * w1.y + r3b.z * w1.z + r3b.w * w1.w;
#pragma unroll
            for (int o = 16; o > 0; o >>= 1) {
                s0 += __shfl_xor_sync(0xffffffffu, s0, o);
                s1 += __shfl_xor_sync(0xffffffffu, s1, o);
                s2 += __shfl_xor_sync(0xffffffffu, s2, o);
                s3 += __shfl_xor_sync(0xffffffffu, s3, o);
            }
            if (lane == 0) {
                ys[e0 + 0] = s0 + cb;
                ys[e0 + 1] = s1 + cb;
                ys[e0 + 2] = s2 + cb;
                ys[e0 + 3] = s3 + cb;
            }
        }
        __syncthreads();

        const float y0 = ys[tid];
        const float y1 = ys[tid + 256];

        // masked logit stores: fire-and-forget
        const float mf = (float)tm;
        out[(size_t)b * 512 + tid]       = y0 * mf;
        out[(size_t)b * 512 + tid + 256] = y1 * mf;

        // gumbel noise (pure ALU)
        const float gb0 = gumbel_from_index((uint32_t)(b * 512 + tid));
        const float gb1 = gumbel_from_index((uint32_t)(b * 512 + tid + 256));

        // ---- max ----
        float m = fmaxf(y0, y1);
#pragma unroll
        for (int o = 16; o > 0; o >>= 1) m = fmaxf(m, __shfl_xor_sync(0xffffffffu, m, o));
        if (lane == 0) wred[warp] = m;
        __syncthreads();
        float maxv = wred[0];
#pragma unroll
        for (int i2 = 1; i2 < 8; i2++) maxv = fmaxf(maxv, wred[i2]);

        // ---- exp + sum ----
        const float e0v = expf(y0 - maxv);
        const float e1v = expf(y1 - maxv);
        float s = e0v + e1v;
#pragma unroll
        for (int o = 16; o > 0; o >>= 1) s += __shfl_xor_sync(0xffffffffu, s, o);
        if (lane == 0) wred2[warp] = s;
        __syncthreads();
        float sumv = wred2[0];
#pragma unroll
        for (int i2 = 1; i2 < 8; i2++) sumv += wred2[i2];

        if (mode != 0) {
            const float sc0 = e0v / sumv + gb0;
            const float sc1 = e1v / sumv + gb1;
            float bv; int bi;
            if (sc1 > sc0) { bv = sc1; bi = tid + 256; } else { bv = sc0; bi = tid; }
#pragma unroll
            for (int o = 16; o > 0; o >>= 1) {
                float ov = __shfl_xor_sync(0xffffffffu, bv, o);
                int   oi = __shfl_xor_sync(0xffffffffu, bi, o);
                if (ov > bv || (ov == bv && oi < bi)) { bv = ov; bi = oi; }
            }
            if (lane == 0) { wv[warp] = bv; wi[warp] = bi; }
            __syncthreads();
            if (tid == 0) {
                float fv = wv[0]; int fi = wi[0];
#pragma unroll
                for (int i2 = 1; i2 < 8; i2++) {
                    if (wv[i2] > fv || (wv[i2] == fv && wi[i2] < fi)) { fv = wv[i2]; fi = wi[i2]; }
                }
                long long id = (long long)fi * (long long)tm;
                if (mode == 1) out[1048576 + b] = (float)id;
                else ((long long*)(out + 1048576))[b] = id;
            }
        }
        __syncthreads();   // protect ys / wred reuse for next q
    }
}

// ---------------------------------------------------------------------------
extern "C" void kernel_launch(void* const* d_in, const int* in_sizes, int n_in,
                              void* d_out, int out_size) {
    const float* ar     = (const float*)d_in[0];
    const int*   utm    = (const int*)d_in[1];
    const int*   tum    = (const int*)d_in[2];
    const float* ee     = (const float*)d_in[3];
    const float* W_func = (const float*)d_in[4];
    const float* b_func = (const float*)d_in[5];
    const float* W_conv = (const float*)d_in[6];
    const float* b_conv = (const float*)d_in[7];
    const float* W_fc1  = (const float*)d_in[8];
    const float* b_fc1  = (const float*)d_in[9];
    const float* W_fc2  = (const float*)d_in[10];
    const float* b_fc2  = (const float*)d_in[11];
    const float* lk     = (const float*)d_in[12];
    // d_in[13] = lstm_recurrent: unused (h0 = 0)
    const float* lb     = (const float*)d_in[14];

    kernelP0<<<128, 256>>>(W_fc1, W_fc2, b_fc1, b_fc2);
    kernelP1<<<512, 256>>>(ar);

    int mode = 0;
    if (out_size >= 1048576 + 4096)      mode = 2;
    else if (out_size >= 1048576 + 2048) mode = 1;
    kernelBF4<<<512, 256>>>(utm, tum, ee, W_func, b_func, W_conv, b_conv,
                            W_fc2, lk, lb, (float*)d_out, mode);
}

// round 8
// speedup vs baseline: 1.0147x; 1.0147x over previous
#include <cuda_runtime.h>
#include <cstdint>
#include <cstddef>

#define B_   2048
#define E_   512
#define EMB_ 256
#define AR_  1024
#define H256_ 256
#define H32_  32
#define NT_   256

// Scratch (no cudaMalloc allowed)
__device__ float g_t[B_ * H256_];   // relu(mask@W_func + b_func)
__device__ float g_v[B_ * H256_];   // ar@W_fc1 + b_fc1

// ---------------------------------------------------------------------------
// Threefry2x32-20, JAX partitionable variant: counter (hi=0, lo=index),
// output = out0 ^ out1, key = (0, 42).
// ---------------------------------------------------------------------------
__device__ __forceinline__ uint32_t rotl32(uint32_t x, int r) {
    return (x << r) | (x >> (32 - r));
}

__device__ __forceinline__ uint32_t threefry_bits(uint32_t k0, uint32_t k1,
                                                  uint32_t c0, uint32_t c1) {
    uint32_t ks2 = k0 ^ k1 ^ 0x1BD11BDAu;
    uint32_t x0 = c0 + k0;
    uint32_t x1 = c1 + k1;
#define TF_RND(r) { x0 += x1; x1 = rotl32(x1, (r)); x1 ^= x0; }
    TF_RND(13) TF_RND(15) TF_RND(26) TF_RND(6)
    x0 += k1;  x1 += ks2 + 1u;
    TF_RND(17) TF_RND(29) TF_RND(16) TF_RND(24)
    x0 += ks2; x1 += k0 + 2u;
    TF_RND(13) TF_RND(15) TF_RND(26) TF_RND(6)
    x0 += k0;  x1 += k1 + 3u;
    TF_RND(17) TF_RND(29) TF_RND(16) TF_RND(24)
    x0 += k1;  x1 += ks2 + 4u;
    TF_RND(13) TF_RND(15) TF_RND(26) TF_RND(6)
    x0 += ks2; x1 += k0 + 5u;
#undef TF_RND
    return x0 ^ x1;
}

__device__ __forceinline__ float gumbel_from_index(uint32_t idx) {
    uint32_t bits = threefry_bits(0u, 42u, 0u, idx);
    float u = __uint_as_float((bits >> 9) | 0x3f800000u) - 1.0f;
    const float tiny = 1.17549435e-38f;
    u = fmaxf(tiny, u + tiny);
    return -logf(-logf(u));
}

// ---------------------------------------------------------------------------
// G: two GEMMs in one launch.
//   blocks [0,256):   g_t = relu(maskf @ W_func + b_func)   (K = 256)
//   blocks [256,512): g_v = ar @ W_fc1 + b_fc1              (K = 1024)
// Tile: BM=32, BN=64, BK=32, 256 threads, 2x4 micro-tile.
// ---------------------------------------------------------------------------
__global__ __launch_bounds__(256)
void kernelG(const float* __restrict__ ar, const int* __restrict__ utm,
             const float* __restrict__ W_func, const float* __restrict__ b_func,
             const float* __restrict__ W_fc1, const float* __restrict__ b_fc1) {
    __shared__ float As[32][33];
    __shared__ float Bs[32][64];

    const int bid = blockIdx.x;
    const bool is_t = bid < 256;
    const int tile = is_t ? bid : bid - 256;
    const int bm = (tile & 63) * 32;
    const int bn = (tile >> 6) * 64;
    const int K = is_t ? NT_ : AR_;
    const float* W = is_t ? W_func : W_fc1;

    const int tid = threadIdx.x;
    const int tx = tid & 15;       // cols tx*4..+3
    const int ty = tid >> 4;       // rows ty*2..+1
    const int lAr = tid >> 3;      // 0..31
    const int lAk = (tid & 7) * 4;

    float acc[2][4];
#pragma unroll
    for (int i = 0; i < 2; i++)
#pragma unroll
        for (int j = 0; j < 4; j++) acc[i][j] = 0.0f;

    for (int k0 = 0; k0 < K; k0 += 32) {
        if (is_t) {
            int4 mi = *(const int4*)(utm + (bm + lAr) * NT_ + k0 + lAk);
            As[lAk + 0][lAr] = (float)mi.x;
            As[lAk + 1][lAr] = (float)mi.y;
            As[lAk + 2][lAr] = (float)mi.z;
            As[lAk + 3][lAr] = (float)mi.w;
        } else {
            float4 av = *(const float4*)(ar + (size_t)(bm + lAr) * AR_ + k0 + lAk);
            As[lAk + 0][lAr] = av.x;
            As[lAk + 1][lAr] = av.y;
            As[lAk + 2][lAr] = av.z;
            As[lAk + 3][lAr] = av.w;
        }
#pragma unroll
        for (int i = 0; i < 2; i++) {
            int f = tid + i * 256;
            int kr = f >> 4, c = (f & 15) * 4;
            *(float4*)&Bs[kr][c] = *(const float4*)(W + (size_t)(k0 + kr) * H256_ + bn + c);
        }
        __syncthreads();
#pragma unroll
        for (int kk = 0; kk < 32; kk++) {
            float a0 = As[kk][ty * 2];
            float a1 = As[kk][ty * 2 + 1];
            float4 b4 = *(const float4*)&Bs[kk][tx * 4];
            acc[0][0] += a0 * b4.x; acc[0][1] += a0 * b4.y;
            acc[0][2] += a0 * b4.z; acc[0][3] += a0 * b4.w;
            acc[1][0] += a1 * b4.x; acc[1][1] += a1 * b4.y;
            acc[1][2] += a1 * b4.z; acc[1][3] += a1 * b4.w;
        }
        __syncthreads();
    }

    float* dst = is_t ? g_t : g_v;
    const float* bias = is_t ? b_func : b_fc1;
#pragma unroll
    for (int i = 0; i < 2; i++) {
        const int row = bm + ty * 2 + i;
#pragma unroll
        for (int j = 0; j < 4; j++) {
            const int col = bn + tx * 4 + j;
            float r = acc[i][j] + bias[col];
            if (is_t) r = fmaxf(r, 0.0f);
            dst[row * H256_ + col] = r;
        }
    }
}

// ---------------------------------------------------------------------------
// BFS: fused, 2 b's per block, grid 1024.
// Slim prologue: z1 = t+v (4KB read); z2 = z1@W_fc2 + b_fc2 (8-warp split);
// LSTM; w = W_conv@q; c0. Then stream ee for both b's (identical to R6).
// ---------------------------------------------------------------------------
__global__ __launch_bounds__(256)
void kernelBFS(const int* __restrict__ tum, const float* __restrict__ ee,
               const float* __restrict__ W_conv, const float* __restrict__ b_conv,
               const float* __restrict__ W_fc2, const float* __restrict__ b_fc2,
               const float* __restrict__ lk, const float* __restrict__ lb,
               float* __restrict__ out, int mode) {
    const int b0 = blockIdx.x * 2;
    const int tid = threadIdx.x;
    const int warp = tid >> 5;
    const int lane = tid & 31;

    __shared__ float s_t[2][H256_];
    __shared__ float s_p[2][8][32];
    __shared__ float s_q[2][32];
    __shared__ float s_w[2][EMB_];
    __shared__ float s_c0[2];
    __shared__ float ys[512];
    __shared__ float wred[8];
    __shared__ float wred2[8];
    __shared__ float wv[8];
    __shared__ int   wi[8];

    // ---- z1 = t + v ----
    s_t[0][tid] = g_t[(b0 + 0) * H256_ + tid] + g_v[(b0 + 0) * H256_ + tid];
    s_t[1][tid] = g_t[(b0 + 1) * H256_ + tid] + g_v[(b0 + 1) * H256_ + tid];
    __syncthreads();

    // ---- z2 partials: warp w covers W_fc2 rows w*32..+31, both b's ----
    {
        float p0 = 0.f, p1 = 0.f;
#pragma unroll
        for (int jj = 0; jj < 32; jj++) {
            const int j = warp * 32 + jj;
            const float wf = W_fc2[j * H32_ + lane];
            p0 += s_t[0][j] * wf;
            p1 += s_t[1][j] * wf;
        }
        s_p[0][warp][lane] = p0;
        s_p[1][warp][lane] = p1;
    }
    __syncthreads();

    // ---- LSTM: warp q in {0,1} ----
    if (warp < 2) {
        float z = b_fc2[lane];
#pragma unroll
        for (int w2 = 0; w2 < 8; w2++) z += s_p[warp][w2][lane];
        float zi = lb[lane];
        float zg = lb[64 + lane];
        float zo = lb[96 + lane];
#pragma unroll
        for (int m = 0; m < 32; m++) {
            float v = __shfl_sync(0xffffffffu, z, m);
            zi += v * lk[m * 128 + lane];
            zg += v * lk[m * 128 + 64 + lane];
            zo += v * lk[m * 128 + 96 + lane];
        }
        float ig = 1.0f / (1.0f + expf(-zi));
        float gg = tanhf(zg);
        float og = 1.0f / (1.0f + expf(-zo));
        float c  = ig * gg;
        float h  = og * tanhf(c);
        s_q[warp][lane] = h;
        float part = b_conv[lane] * h;
#pragma unroll
        for (int s = 16; s > 0; s >>= 1) part += __shfl_xor_sync(0xffffffffu, part, s);
        if (lane == 0) s_c0[warp] = part;
    }
    __syncthreads();

    // ---- w = W_conv @ q, row per thread, shared across both b's ----
    {
        const float* wr = W_conv + tid * H32_;
        float4 wc[8];
#pragma unroll
        for (int m = 0; m < 8; m++) wc[m] = *(const float4*)(wr + m * 4);
#pragma unroll
        for (int q = 0; q < 2; q++) {
            float s0 = 0.f, s1 = 0.f;
#pragma unroll
            for (int m = 0; m < 8; m++) {
                s0 += wc[m].x * s_q[q][m * 4 + 0] + wc[m].y * s_q[q][m * 4 + 1];
                s1 += wc[m].z * s_q[q][m * 4 + 2] + wc[m].w * s_q[q][m * 4 + 3];
            }
            s_w[q][tid] = s0 + s1;
        }
    }
    __syncthreads();

    // =========================== Stream both b's ===========================
    for (int q = 0; q < 2; q++) {
        const int b = b0 + q;
        const float4 w0 = *(const float4*)(&s_w[q][4 * lane]);
        const float4 w1 = *(const float4*)(&s_w[q][128 + 4 * lane]);
        const float cb = s_c0[q];
        const int tm = tum[b];
        const float4* eb = (const float4*)(ee + (size_t)b * E_ * EMB_);

#pragma unroll
        for (int it = 0; it < 16; it++) {
            const int e0 = it * 32 + warp * 4;
            float4 r0a = __ldcs(eb + (size_t)(e0 + 0) * 64 + lane);
            float4 r0b = __ldcs(eb + (size_t)(e0 + 0) * 64 + 32 + lane);
            float4 r1a = __ldcs(eb + (size_t)(e0 + 1) * 64 + lane);
            float4 r1b = __ldcs(eb + (size_t)(e0 + 1) * 64 + 32 + lane);
            float4 r2a = __ldcs(eb + (size_t)(e0 + 2) * 64 + lane);
            float4 r2b = __ldcs(eb + (size_t)(e0 + 2) * 64 + 32 + lane);
            float4 r3a = __ldcs(eb + (size_t)(e0 + 3) * 64 + lane);
            float4 r3b = __ldcs(eb + (size_t)(e0 + 3) * 64 + 32 + lane);

            float s0 = r0a.x * w0.x + r0a.y * w0.y + r0a.z * w0.z + r0a.w * w0.w
                     + r0b.x * w1.x + r0b.y * w1.y + r0b.z * w1.z + r0b.w * w1.w;
            float s1 = r1a.x * w0.x + r1a.y * w0.y + r1a.z * w0.z + r1a.w * w0.w
                     + r1b.x * w1.x + r1b.y * w1.y + r1b.z * w1.z + r1b.w * w1.w;
            float s2 = r2a.x * w0.x + r2a.y * w0.y + r2a.z * w0.z + r2a.w * w0.w
                     + r2b.x * w1.x + r2b.y * w1.y + r2b.z * w1.z + r2b.w * w1.w;
            float s3 = r3a.x * w0.x + r3a.y * w0.y + r3a.z * w0.z + r3a.w * w0.w
                     + r3b.x * w1.x + r3b.y * w1.y + r3b.z * w1.z + r3b.w * w1.w;
#pragma unroll
            for (int o = 16; o > 0; o >>= 1) {
                s0 += __shfl_xor_sync(0xffffffffu, s0, o);
                s1 += __shfl_xor_sync(0xffffffffu, s1, o);
                s2 += __shfl_xor_sync(0xffffffffu, s2, o);
                s3 += __shfl_xor_sync(0xffffffffu, s3, o);
            }
            if (lane == 0) {
                ys[e0 + 0] = s0 + cb;
                ys[e0 + 1] = s1 + cb;
                ys[e0 + 2] = s2 + cb;
                ys[e0 + 3] = s3 + cb;
            }
        }
        __syncthreads();

        const float y0 = ys[tid];
        const float y1 = ys[tid + 256];

        // masked logit stores: fire-and-forget
        const float mf = (float)tm;
        out[(size_t)b * 512 + tid]       = y0 * mf;
        out[(size_t)b * 512 + tid + 256] = y1 * mf;

        // gumbel noise (pure ALU)
        const float gb0 = gumbel_from_index((uint32_t)(b * 512 + tid));
        const float gb1 = gumbel_from_index((uint32_t)(b * 512 + tid + 256));

        // ---- max ----
        float m = fmaxf(y0, y1);
#pragma unroll
        for (int o = 16; o > 0; o >>= 1) m = fmaxf(m, __shfl_xor_sync(0xffffffffu, m, o));
        if (lane == 0) wred[warp] = m;
        __syncthreads();
        float maxv = wred[0];
#pragma unroll
        for (int i2 = 1; i2 < 8; i2++) maxv = fmaxf(maxv, wred[i2]);

        // ---- exp + sum ----
        const float e0v = expf(y0 - maxv);
        const float e1v = expf(y1 - maxv);
        float s = e0v + e1v;
#pragma unroll
        for (int o = 16; o > 0; o >>= 1) s += __shfl_xor_sync(0xffffffffu, s, o);
        if (lane == 0) wred2[warp] = s;
        __syncthreads();
        float sumv = wred2[0];
#pragma unroll
        for (int i2 = 1; i2 < 8; i2++) sumv += wred2[i2];

        if (mode != 0) {
            const float sc0 = e0v / sumv + gb0;
            const float sc1 = e1v / sumv + gb1;
            float bv; int bi;
            if (sc1 > sc0) { bv = sc1; bi = tid + 256; } else { bv = sc0; bi = tid; }
#pragma unroll
            for (int o = 16; o > 0; o >>= 1) {
                float ov = __shfl_xor_sync(0xffffffffu, bv, o);
                int   oi = __shfl_xor_sync(0xffffffffu, bi, o);
                if (ov > bv || (ov == bv && oi < bi)) { bv = ov; bi = oi; }
            }
            if (lane == 0) { wv[warp] = bv; wi[warp] = bi; }
            __syncthreads();
            if (tid == 0) {
                float fv = wv[0]; int fi = wi[0];
#pragma unroll
                for (int i2 = 1; i2 < 8; i2++) {
                    if (wv[i2] > fv || (wv[i2] == fv && wi[i2] < fi)) { fv = wv[i2]; fi = wi[i2]; }
                }
                long long id = (long long)fi * (long long)tm;
                if (mode == 1) out[1048576 + b] = (float)id;
                else ((long long*)(out + 1048576))[b] = id;
            }
        }
        __syncthreads();   // protect ys / wred reuse for next q
    }
}

// ---------------------------------------------------------------------------
extern "C" void kernel_launch(void* const* d_in, const int* in_sizes, int n_in,
                              void* d_out, int out_size) {
    const float* ar     = (const float*)d_in[0];
    const int*   utm    = (const int*)d_in[1];
    const int*   tum    = (const int*)d_in[2];
    const float* ee     = (const float*)d_in[3];
    const float* W_func = (const float*)d_in[4];
    const float* b_func = (const float*)d_in[5];
    const float* W_conv = (const float*)d_in[6];
    const float* b_conv = (const float*)d_in[7];
    const float* W_fc1  = (const float*)d_in[8];
    const float* b_fc1  = (const float*)d_in[9];
    const float* W_fc2  = (const float*)d_in[10];
    const float* b_fc2  = (const float*)d_in[11];
    const float* lk     = (const float*)d_in[12];
    // d_in[13] = lstm_recurrent: unused (h0 = 0)
    const float* lb     = (const float*)d_in[14];

    kernelG<<<512, 256>>>(ar, utm, W_func, b_func, W_fc1, b_fc1);

    int mode = 0;
    if (out_size >= 1048576 + 4096)      mode = 2;
    else if (out_size >= 1048576 + 2048) mode = 1;
    kernelBFS<<<1024, 256>>>(tum, ee, W_conv, b_conv, W_fc2, b_fc2,
                             lk, lb, (float*)d_out, mode);
}

// round 9
// speedup vs baseline: 1.3150x; 1.2959x over previous
#include <cuda_runtime.h>
#include <cstdint>
#include <cstddef>

#define B_   2048
#define E_   512
#define EMB_ 256
#define AR_  1024
#define H256_ 256
#define H32_  32
#define NT_   256

// Scratch (no cudaMalloc allowed)
__device__ float g_t[B_ * H256_];    // relu(mask@W_func + b_func)
__device__ float g_W12[AR_ * H32_];  // W_fc1 @ W_fc2
__device__ float g_bvec[H32_];       // b_fc1 @ W_fc2 + b_fc2

// ---------------------------------------------------------------------------
// Threefry2x32-20, JAX partitionable variant: counter (hi=0, lo=index),
// output = out0 ^ out1, key = (0, 42).
// ---------------------------------------------------------------------------
__device__ __forceinline__ uint32_t rotl32(uint32_t x, int r) {
    return (x << r) | (x >> (32 - r));
}

__device__ __forceinline__ uint32_t threefry_bits(uint32_t k0, uint32_t k1,
                                                  uint32_t c0, uint32_t c1) {
    uint32_t ks2 = k0 ^ k1 ^ 0x1BD11BDAu;
    uint32_t x0 = c0 + k0;
    uint32_t x1 = c1 + k1;
#define TF_RND(r) { x0 += x1; x1 = rotl32(x1, (r)); x1 ^= x0; }
    TF_RND(13) TF_RND(15) TF_RND(26) TF_RND(6)
    x0 += k1;  x1 += ks2 + 1u;
    TF_RND(17) TF_RND(29) TF_RND(16) TF_RND(24)
    x0 += ks2; x1 += k0 + 2u;
    TF_RND(13) TF_RND(15) TF_RND(26) TF_RND(6)
    x0 += k0;  x1 += k1 + 3u;
    TF_RND(17) TF_RND(29) TF_RND(16) TF_RND(24)
    x0 += k1;  x1 += ks2 + 4u;
    TF_RND(13) TF_RND(15) TF_RND(26) TF_RND(6)
    x0 += ks2; x1 += k0 + 5u;
#undef TF_RND
    return x0 ^ x1;
}

__device__ __forceinline__ float gumbel_from_index(uint32_t idx) {
    uint32_t bits = threefry_bits(0u, 42u, 0u, idx);
    float u = __uint_as_float((bits >> 9) | 0x3f800000u) - 1.0f;
    const float tiny = 1.17549435e-38f;
    u = fmaxf(tiny, u + tiny);
    return -logf(-logf(u));
}

// ---------------------------------------------------------------------------
// J: one launch, two independent jobs.
//   blocks [0,256):   g_t = relu(maskf @ W_func + b_func)   (Q1 tiling,
//                     BM=32, BN=64, BK=32, 2x4 micro-tile)
//   blocks [256,384): g_W12 rows (warp-per-row, K=256) + g_bvec
// ---------------------------------------------------------------------------
__global__ __launch_bounds__(256)
void kernelJ(const int* __restrict__ utm,
             const float* __restrict__ W_func, const float* __restrict__ b_func,
             const float* __restrict__ W_fc1, const float* __restrict__ W_fc2,
             const float* __restrict__ b_fc1, const float* __restrict__ b_fc2) {
    const int bid = blockIdx.x;
    const int tid = threadIdx.x;

    if (bid < 256) {
        // ---------------- mask GEMM -> g_t ----------------
        __shared__ float As[32][33];
        __shared__ float Bs[32][64];

        const int bm = (bid & 63) * 32;
        const int bn = (bid >> 6) * 64;
        const int tx = tid & 15;
        const int ty = tid >> 4;
        const int lAr = tid >> 3;
        const int lAk = (tid & 7) * 4;

        float acc[2][4];
#pragma unroll
        for (int i = 0; i < 2; i++)
#pragma unroll
            for (int j = 0; j < 4; j++) acc[i][j] = 0.0f;

        for (int k0 = 0; k0 < NT_; k0 += 32) {
            int4 mi = *(const int4*)(utm + (bm + lAr) * NT_ + k0 + lAk);
            As[lAk + 0][lAr] = (float)mi.x;
            As[lAk + 1][lAr] = (float)mi.y;
            As[lAk + 2][lAr] = (float)mi.z;
            As[lAk + 3][lAr] = (float)mi.w;
#pragma unroll
            for (int i = 0; i < 2; i++) {
                int f = tid + i * 256;
                int kr = f >> 4, c = (f & 15) * 4;
                *(float4*)&Bs[kr][c] =
                    *(const float4*)(W_func + (size_t)(k0 + kr) * H256_ + bn + c);
            }
            __syncthreads();
#pragma unroll
            for (int kk = 0; kk < 32; kk++) {
                float a0 = As[kk][ty * 2];
                float a1 = As[kk][ty * 2 + 1];
                float4 b4 = *(const float4*)&Bs[kk][tx * 4];
                acc[0][0] += a0 * b4.x; acc[0][1] += a0 * b4.y;
                acc[0][2] += a0 * b4.z; acc[0][3] += a0 * b4.w;
                acc[1][0] += a1 * b4.x; acc[1][1] += a1 * b4.y;
                acc[1][2] += a1 * b4.z; acc[1][3] += a1 * b4.w;
            }
            __syncthreads();
        }

#pragma unroll
        for (int i = 0; i < 2; i++) {
            const int row = bm + ty * 2 + i;
#pragma unroll
            for (int j = 0; j < 4; j++) {
                const int col = bn + tx * 4 + j;
                g_t[row * H256_ + col] = fmaxf(acc[i][j] + b_func[col], 0.0f);
            }
        }
    } else {
        // ---------------- W12 rows + bvec ----------------
        const int warp = tid >> 5;
        const int lane = tid & 31;
        const int r = (bid - 256) * 8 + warp;

        const float* frow = W_fc1 + (size_t)r * H256_;
        float a0 = 0.f, a1 = 0.f, a2 = 0.f, a3 = 0.f;
#pragma unroll 8
        for (int k = 0; k < H256_; k += 4) {
            float4 f = *(const float4*)(frow + k);
            a0 += f.x * W_fc2[(k + 0) * H32_ + lane];
            a1 += f.y * W_fc2[(k + 1) * H32_ + lane];
            a2 += f.z * W_fc2[(k + 2) * H32_ + lane];
            a3 += f.w * W_fc2[(k + 3) * H32_ + lane];
        }
        g_W12[r * H32_ + lane] = (a0 + a1) + (a2 + a3);

        if (bid == 256 && warp == 0) {
            float b0 = b_fc2[lane];
#pragma unroll 8
            for (int k = 0; k < H256_; k++) b0 += b_fc1[k] * W_fc2[k * H32_ + lane];
            g_bvec[lane] = b0;
        }
    }
}

// ---------------------------------------------------------------------------
// BF2p: fused, 2 b's per block, grid 1024.
// Prologue: load t (2KB); z2 partials = t@W_fc2 (per-warp 32 rows) +
// ar@W12 (per-warp 128 k's, W12 L1/L2-hot, both b's in one pass); LSTM;
// w = W_conv@q; c0. Then the proven ee stream.
// ---------------------------------------------------------------------------
__global__ __launch_bounds__(256)
void kernelBF2p(const float* __restrict__ ar, const int* __restrict__ tum,
                const float* __restrict__ ee,
                const float* __restrict__ W_conv, const float* __restrict__ b_conv,
                const float* __restrict__ W_fc2,
                const float* __restrict__ lk, const float* __restrict__ lb,
                float* __restrict__ out, int mode) {
    const int b0 = blockIdx.x * 2;
    const int tid = threadIdx.x;
    const int warp = tid >> 5;
    const int lane = tid & 31;

    __shared__ float s_t[2][H256_];
    __shared__ float s_p[2][8][32];
    __shared__ float s_q[2][32];
    __shared__ float s_w[2][EMB_];
    __shared__ float s_c0[2];
    __shared__ float ys[512];
    __shared__ float wred[8];
    __shared__ float wred2[8];
    __shared__ float wv[8];
    __shared__ int   wi[8];

    // ---- load t ----
    s_t[0][tid] = g_t[(b0 + 0) * H256_ + tid];
    s_t[1][tid] = g_t[(b0 + 1) * H256_ + tid];
    __syncthreads();

    // ---- z2 partials: t-part (warp's 32 W_fc2 rows) + ar@W12 (warp's 128 k's)
    {
        float p0 = 0.f, p1 = 0.f;
#pragma unroll
        for (int jj = 0; jj < 32; jj++) {
            const int j = warp * 32 + jj;
            const float wf = W_fc2[j * H32_ + lane];
            p0 += s_t[0][j] * wf;
            p1 += s_t[1][j] * wf;
        }
        // ar fold: both b's share each W12 load
        const float* arowA = ar + (size_t)(b0 + 0) * AR_ + warp * 128;
        const float* arowB = ar + (size_t)(b0 + 1) * AR_ + warp * 128;
        const float* w12p = g_W12 + (size_t)(warp * 128) * H32_;
        float qa0 = 0.f, qa1 = 0.f, qa2 = 0.f, qa3 = 0.f;
        float qb0 = 0.f, qb1 = 0.f, qb2 = 0.f, qb3 = 0.f;
#pragma unroll 4
        for (int r = 0; r < 128; r += 4) {
            float4 aA = *(const float4*)(arowA + r);
            float4 aB = *(const float4*)(arowB + r);
            const float w0v = w12p[(r + 0) * H32_ + lane];
            const float w1v = w12p[(r + 1) * H32_ + lane];
            const float w2v = w12p[(r + 2) * H32_ + lane];
            const float w3v = w12p[(r + 3) * H32_ + lane];
            qa0 += aA.x * w0v; qa1 += aA.y * w1v;
            qa2 += aA.z * w2v; qa3 += aA.w * w3v;
            qb0 += aB.x * w0v; qb1 += aB.y * w1v;
            qb2 += aB.z * w2v; qb3 += aB.w * w3v;
        }
        s_p[0][warp][lane] = p0 + (qa0 + qa1) + (qa2 + qa3);
        s_p[1][warp][lane] = p1 + (qb0 + qb1) + (qb2 + qb3);
    }
    __syncthreads();

    // ---- LSTM: warp q in {0,1} ----
    if (warp < 2) {
        float z = g_bvec[lane];
#pragma unroll
        for (int w2 = 0; w2 < 8; w2++) z += s_p[warp][w2][lane];
        float zi = lb[lane];
        float zg = lb[64 + lane];
        float zo = lb[96 + lane];
#pragma unroll
        for (int m = 0; m < 32; m++) {
            float v = __shfl_sync(0xffffffffu, z, m);
            zi += v * lk[m * 128 + lane];
            zg += v * lk[m * 128 + 64 + lane];
            zo += v * lk[m * 128 + 96 + lane];
        }
        float ig = 1.0f / (1.0f + expf(-zi));
        float gg = tanhf(zg);
        float og = 1.0f / (1.0f + expf(-zo));
        float c  = ig * gg;
        float h  = og * tanhf(c);
        s_q[warp][lane] = h;
        float part = b_conv[lane] * h;
#pragma unroll
        for (int s = 16; s > 0; s >>= 1) part += __shfl_xor_sync(0xffffffffu, part, s);
        if (lane == 0) s_c0[warp] = part;
    }
    __syncthreads();

    // ---- w = W_conv @ q, row per thread, shared across both b's ----
    {
        const float* wr = W_conv + tid * H32_;
        float4 wc[8];
#pragma unroll
        for (int m = 0; m < 8; m++) wc[m] = *(const float4*)(wr + m * 4);
#pragma unroll
        for (int q = 0; q < 2; q++) {
            float s0 = 0.f, s1 = 0.f;
#pragma unroll
            for (int m = 0; m < 8; m++) {
                s0 += wc[m].x * s_q[q][m * 4 + 0] + wc[m].y * s_q[q][m * 4 + 1];
                s1 += wc[m].z * s_q[q][m * 4 + 2] + wc[m].w * s_q[q][m * 4 + 3];
            }
            s_w[q][tid] = s0 + s1;
        }
    }
    __syncthreads();

    // =========================== Stream both b's ===========================
    for (int q = 0; q < 2; q++) {
        const int b = b0 + q;
        const float4 w0 = *(const float4*)(&s_w[q][4 * lane]);
        const float4 w1 = *(const float4*)(&s_w[q][128 + 4 * lane]);
        const float cb = s_c0[q];
        const int tm = tum[b];
        const float4* eb = (const float4*)(ee + (size_t)b * E_ * EMB_);

#pragma unroll
        for (int it = 0; it < 16; it++) {
            const int e0 = it * 32 + warp * 4;
            float4 r0a = __ldcs(eb + (size_t)(e0 + 0) * 64 + lane);
            float4 r0b = __ldcs(eb + (size_t)(e0 + 0) * 64 + 32 + lane);
            float4 r1a = __ldcs(eb + (size_t)(e0 + 1) * 64 + lane);
            float4 r1b = __ldcs(eb + (size_t)(e0 + 1) * 64 + 32 + lane);
            float4 r2a = __ldcs(eb + (size_t)(e0 + 2) * 64 + lane);
            float4 r2b = __ldcs(eb + (size_t)(e0 + 2) * 64 + 32 + lane);
            float4 r3a = __ldcs(eb + (size_t)(e0 + 3) * 64 + lane);
            float4 r3b = __ldcs(eb + (size_t)(e0 + 3) * 64 + 32 + lane);

            float s0 = r0a.x * w0.x + r0a.y * w0.y + r0a.z * w0.z + r0a.w * w0.w
                     + r0b.x * w1.x + r0b.y * w1.y + r0b.z * w1.z + r0b.w * w1.w;
            float s1 = r1a.x * w0.x + r1a.y * w0.y + r1a.z * w0.z + r1a.w * w0.w
                     + r1b.x * w1.x + r1b.y * w1.y + r1b.z * w1.z + r1b.w * w1.w;
            float s2 = r2a.x * w0.x + r2a.y * w0.y + r2a.z * w0.z + r2a.w * w0.w
                     + r2b.x * w1.x + r2b.y * w1.y + r2b.z * w1.z + r2b.w * w1.w;
            float s3 = r3a.x * w0.x + r3a.y * w0.y + r3a.z * w0.z + r3a.w * w0.w
                     + r3b.x * w1.x + r3b.y * w1.y + r3b.z * w1.z + r3b.w * w1.w;
#pragma unroll
            for (int o = 16; o > 0; o >>= 1) {
                s0 += __shfl_xor_sync(0xffffffffu, s0, o);
                s1 += __shfl_xor_sync(0xffffffffu, s1, o);
                s2 += __shfl_xor_sync(0xffffffffu, s2, o);
                s3 += __shfl_xor_sync(0xffffffffu, s3, o);
            }
            if (lane == 0) {
                ys[e0 + 0] = s0 + cb;
                ys[e0 + 1] = s1 + cb;
                ys[e0 + 2] = s2 + cb;
                ys[e0 + 3] = s3 + cb;
            }
        }
        __syncthreads();

        const float y0 = ys[tid];
        const float y1 = ys[tid + 256];

        // masked logit stores: fire-and-forget
        const float mf = (float)tm;
        out[(size_t)b * 512 + tid]       = y0 * mf;
        out[(size_t)b * 512 + tid + 256] = y1 * mf;

        // gumbel noise (pure ALU)
        const float gb0 = gumbel_from_index((uint32_t)(b * 512 + tid));
        const float gb1 = gumbel_from_index((uint32_t)(b * 512 + tid + 256));

        // ---- max ----
        float m = fmaxf(y0, y1);
#pragma unroll
        for (int o = 16; o > 0; o >>= 1) m = fmaxf(m, __shfl_xor_sync(0xffffffffu, m, o));
        if (lane == 0) wred[warp] = m;
        __syncthreads();
        float maxv = wred[0];
#pragma unroll
        for (int i2 = 1; i2 < 8; i2++) maxv = fmaxf(maxv, wred[i2]);

        // ---- exp + sum ----
        const float e0v = expf(y0 - maxv);
        const float e1v = expf(y1 - maxv);
        float s = e0v + e1v;
#pragma unroll
        for (int o = 16; o > 0; o >>= 1) s += __shfl_xor_sync(0xffffffffu, s, o);
        if (lane == 0) wred2[warp] = s;
        __syncthreads();
        float sumv = wred2[0];
#pragma unroll
        for (int i2 = 1; i2 < 8; i2++) sumv += wred2[i2];

        if (mode != 0) {
            const float sc0 = e0v / sumv + gb0;
            const float sc1 = e1v / sumv + gb1;
            float bv; int bi;
            if (sc1 > sc0) { bv = sc1; bi = tid + 256; } else { bv = sc0; bi = tid; }
#pragma unroll
            for (int o = 16; o > 0; o >>= 1) {
                float ov = __shfl_xor_sync(0xffffffffu, bv, o);
                int   oi = __shfl_xor_sync(0xffffffffu, bi, o);
                if (ov > bv || (ov == bv && oi < bi)) { bv = ov; bi = oi; }
            }
            if (lane == 0) { wv[warp] = bv; wi[warp] = bi; }
            __syncthreads();
            if (tid == 0) {
                float fv = wv[0]; int fi = wi[0];
#pragma unroll
                for (int i2 = 1; i2 < 8; i2++) {
                    if (wv[i2] > fv || (wv[i2] == fv && wi[i2] < fi)) { fv = wv[i2]; fi = wi[i2]; }
                }
                long long id = (long long)fi * (long long)tm;
                if (mode == 1) out[1048576 + b] = (float)id;
                else ((long long*)(out + 1048576))[b] = id;
            }
        }
        __syncthreads();   // protect ys / wred reuse for next q
    }
}

// ---------------------------------------------------------------------------
extern "C" void kernel_launch(void* const* d_in, const int* in_sizes, int n_in,
                              void* d_out, int out_size) {
    const float* ar     = (const float*)d_in[0];
    const int*   utm    = (const int*)d_in[1];
    const int*   tum    = (const int*)d_in[2];
    const float* ee     = (const float*)d_in[3];
    const float* W_func = (const float*)d_in[4];
    const float* b_func = (const float*)d_in[5];
    const float* W_conv = (const float*)d_in[6];
    const float* b_conv = (const float*)d_in[7];
    const float* W_fc1  = (const float*)d_in[8];
    const float* b_fc1  = (const float*)d_in[9];
    const float* W_fc2  = (const float*)d_in[10];
    const float* b_fc2  = (const float*)d_in[11];
    const float* lk     = (const float*)d_in[12];
    // d_in[13] = lstm_recurrent: unused (h0 = 0)
    const float* lb     = (const float*)d_in[14];

    kernelJ<<<384, 256>>>(utm, W_func, b_func, W_fc1, W_fc2, b_fc1, b_fc2);

    int mode = 0;
    if (out_size >= 1048576 + 4096)      mode = 2;
    else if (out_size >= 1048576 + 2048) mode = 1;
    kernelBF2p<<<1024, 256>>>(ar, tum, ee, W_conv, b_conv, W_fc2,
                              lk, lb, (float*)d_out, mode);
}